// round 1
// baseline (speedup 1.0000x reference)
#include <cuda_runtime.h>
#include <math.h>

// ---------------- problem constants ----------------
constexpr int kB = 32;
constexpr int kH = 32;
constexpr int kW = 32;
constexpr int kC = 512;
constexpr int kHeads = 16;
constexpr int kWS = 8;
constexpr int kSS = 4;
constexpr int kN = 64;            // tokens per window
constexpr int kNW = 16;           // windows per image
constexpr int kHD = 32;           // head dim
constexpr int kL = kH * kW;       // 1024
constexpr int kRows = kB * kL;    // 32768

// ---------------- scratch (static device allocations are the sanctioned path) ----
__device__ __align__(16) float g_ada[kB * 6 * kC];
__device__ __align__(16) float g_hw[(size_t)kRows * kC];
__device__ __align__(16) float g_qkv[(size_t)kRows * 3 * kC];
__device__ __align__(16) float g_attn[(size_t)kRows * kC];
__device__ __align__(16) float g_proj[(size_t)kRows * kC];
__device__ __align__(16) float g_x2[(size_t)kRows * kC];
__device__ __align__(16) float g_m[(size_t)kRows * kC];
__device__ __align__(16) float g_fc1[(size_t)kRows * 4 * kC];

// ---------------- adaLN: ada = silu(cond) @ ada_w^T + ada_b ----------------
__global__ void ada_kernel(const float* __restrict__ cond,
                           const float* __restrict__ ada_w,
                           const float* __restrict__ ada_b) {
    int b = blockIdx.x;
    __shared__ float sc[kC];
    for (int i = threadIdx.x; i < kC; i += blockDim.x) {
        float c = cond[b * kC + i];
        sc[i] = c / (1.f + expf(-c));
    }
    __syncthreads();
    for (int n = threadIdx.x; n < 6 * kC; n += blockDim.x) {
        const float* wr = ada_w + (size_t)n * kC;
        float acc = 0.f;
        #pragma unroll 8
        for (int k = 0; k < kC; ++k) acc += sc[k] * wr[k];
        g_ada[b * 6 * kC + n] = acc + ada_b[n];
    }
}

// ---------------- LN + modulate (+ optional roll & window-partition gather) ----
// mode 0: output row r is a window-token row; gather source from rolled image.
// mode 1: identity row mapping (MLP branch).
__global__ void ln_mod_kernel(const float* __restrict__ x,
                              const float* __restrict__ lnw,
                              const float* __restrict__ lnb,
                              float* __restrict__ out,
                              int mode, int sh_off, int sc_off) {
    int r = blockIdx.x;
    int b, src;
    if (mode == 0) {
        int win = r >> 6, t = r & 63;
        b = win >> 4;
        int nw_ = win & 15;
        int hb = nw_ >> 2, wb = nw_ & 3;
        int i = hb * 8 + (t >> 3), j = wb * 8 + (t & 7);
        int si = (i + kSS) & 31, sj = (j + kSS) & 31;   // roll(-SS) gather
        src = b * kL + si * 32 + sj;
    } else {
        b = r >> 10;
        src = r;
    }
    int tid = threadIdx.x;  // 128 threads, 4 floats each
    float4 v = ((const float4*)(x + (size_t)src * kC))[tid];
    float s = v.x + v.y + v.z + v.w;
    float ss = v.x * v.x + v.y * v.y + v.z * v.z + v.w * v.w;
    #pragma unroll
    for (int o = 16; o; o >>= 1) {
        s  += __shfl_down_sync(0xffffffffu, s, o);
        ss += __shfl_down_sync(0xffffffffu, ss, o);
    }
    __shared__ float ps[4], pss[4], mv[2];
    int wp = tid >> 5;
    if ((tid & 31) == 0) { ps[wp] = s; pss[wp] = ss; }
    __syncthreads();
    if (tid == 0) {
        float S = ps[0] + ps[1] + ps[2] + ps[3];
        float S2 = pss[0] + pss[1] + pss[2] + pss[3];
        float mu = S / kC;
        float var = S2 / kC - mu * mu;
        mv[0] = mu;
        mv[1] = rsqrtf(var + 1e-5f);
    }
    __syncthreads();
    float mu = mv[0], rs = mv[1];
    int c0 = tid * 4;
    const float* sh = g_ada + b * 6 * kC + sh_off;
    const float* sc = g_ada + b * 6 * kC + sc_off;
    float vv[4] = {v.x, v.y, v.z, v.w};
    float o4[4];
    #pragma unroll
    for (int u = 0; u < 4; ++u) {
        float val = (vv[u] - mu) * rs * lnw[c0 + u] + lnb[c0 + u];
        o4[u] = val * (1.f + sc[c0 + u]) + sh[c0 + u];
    }
    ((float4*)(out + (size_t)r * kC))[tid] = make_float4(o4[0], o4[1], o4[2], o4[3]);
}

// ---------------- generic NT SGEMM: C[M,N] = A[M,K] @ Bw[N,K]^T + bias ----------
// epi 0: bias only.  epi 1: bias + exact GELU.  epi 2: res + gate*(bias+acc).
__global__ __launch_bounds__(256) void gemm_nt(
        const float* __restrict__ A, const float* __restrict__ Bw,
        const float* __restrict__ bias, float* __restrict__ C,
        int M, int N, int K, int epi,
        const float* __restrict__ res, int gate_off) {
    __shared__ float As[16][128];
    __shared__ float Bs[16][128];
    int tid = threadIdx.x;
    int tx = tid & 15, ty = tid >> 4;
    float acc[8][8];
    #pragma unroll
    for (int i = 0; i < 8; ++i)
        #pragma unroll
        for (int j = 0; j < 8; ++j) acc[i][j] = 0.f;

    const float* Ag = A + (size_t)(blockIdx.y * 128) * K;
    const float* Bg = Bw + (size_t)(blockIdx.x * 128) * K;
    int lr = tid >> 2, lc = (tid & 3) << 2;

    for (int kt = 0; kt < K; kt += 16) {
        #pragma unroll
        for (int h = 0; h < 2; ++h) {
            int row = lr + h * 64;
            float4 va = *(const float4*)(Ag + (size_t)row * K + kt + lc);
            As[lc + 0][row] = va.x; As[lc + 1][row] = va.y;
            As[lc + 2][row] = va.z; As[lc + 3][row] = va.w;
            float4 vb = *(const float4*)(Bg + (size_t)row * K + kt + lc);
            Bs[lc + 0][row] = vb.x; Bs[lc + 1][row] = vb.y;
            Bs[lc + 2][row] = vb.z; Bs[lc + 3][row] = vb.w;
        }
        __syncthreads();
        #pragma unroll
        for (int k = 0; k < 16; ++k) {
            float ar[8], br[8];
            #pragma unroll
            for (int i = 0; i < 8; ++i) ar[i] = As[k][ty * 8 + i];
            #pragma unroll
            for (int j = 0; j < 8; ++j) br[j] = Bs[k][tx * 8 + j];
            #pragma unroll
            for (int i = 0; i < 8; ++i)
                #pragma unroll
                for (int j = 0; j < 8; ++j) acc[i][j] += ar[i] * br[j];
        }
        __syncthreads();
    }

    int r0 = blockIdx.y * 128 + ty * 8;
    int c0 = blockIdx.x * 128 + tx * 8;
    #pragma unroll
    for (int i = 0; i < 8; ++i) {
        int r = r0 + i;
        float vals[8];
        #pragma unroll
        for (int j = 0; j < 8; ++j) {
            int c = c0 + j;
            float v = acc[i][j] + bias[c];
            if (epi == 1) {
                v = 0.5f * v * (1.f + erff(v * 0.70710678118654752f));
            } else if (epi == 2) {
                int b = r >> 10;
                v = res[(size_t)r * kC + c] + g_ada[b * 6 * kC + gate_off + c] * v;
            }
            vals[j] = v;
        }
        float4* cp = (float4*)(C + (size_t)r * N + c0);
        cp[0] = make_float4(vals[0], vals[1], vals[2], vals[3]);
        cp[1] = make_float4(vals[4], vals[5], vals[6], vals[7]);
    }
}

// ---------------- window attention: one block per (window, head) ----------------
__global__ __launch_bounds__(256) void attn_kernel(const float* __restrict__ rpb) {
    int win = blockIdx.x, head = blockIdx.y;
    __shared__ float q[64][32], kk[64][32], vv[64][32];
    __shared__ float s[64][65];
    __shared__ int sid[64];
    int tid = threadIdx.x;

    const float* base = g_qkv + (size_t)win * 64 * 1536 + head * 32;
    #pragma unroll
    for (int u = 0; u < 8; ++u) {
        int idx = tid + u * 256;
        int n = idx >> 5, d = idx & 31;
        size_t off = (size_t)n * 1536 + d;
        q[n][d]  = base[off];
        kk[n][d] = base[off + 512];
        vv[n][d] = base[off + 1024];
    }
    if (tid < 64) {
        int nw_ = win & 15, hb = nw_ >> 2, wb = nw_ & 3;
        int i = hb * 8 + (tid >> 3), j = wb * 8 + (tid & 7);
        int ri = i < 24 ? 0 : (i < 28 ? 1 : 2);
        int rj = j < 24 ? 0 : (j < 28 ? 1 : 2);
        sid[tid] = ri * 3 + rj;
    }
    __syncthreads();

    const float scale = 0.17677669529663687f;  // 1/sqrt(32)
    #pragma unroll
    for (int u = 0; u < 16; ++u) {
        int idx = tid + u * 256;
        int n = idx >> 6, m = idx & 63;
        float acc = 0.f;
        #pragma unroll
        for (int d = 0; d < 32; ++d) acc += q[n][d] * kk[m][d];
        int di = (n >> 3) - (m >> 3) + 7;
        int dj = (n & 7) - (m & 7) + 7;
        float bias_ = rpb[(di * 15 + dj) * kHeads + head];
        float msk = (sid[n] != sid[m]) ? -100.f : 0.f;
        s[n][m] = acc * scale + bias_ + msk;
    }
    __syncthreads();

    if (tid < 64) {
        float mx = -1e30f;
        #pragma unroll 8
        for (int m = 0; m < 64; ++m) mx = fmaxf(mx, s[tid][m]);
        float sum = 0.f;
        #pragma unroll 8
        for (int m = 0; m < 64; ++m) { float e = expf(s[tid][m] - mx); s[tid][m] = e; sum += e; }
        float inv = 1.f / sum;
        #pragma unroll 8
        for (int m = 0; m < 64; ++m) s[tid][m] *= inv;
    }
    __syncthreads();

    float* outp = g_attn + (size_t)win * 64 * kC + head * 32;
    #pragma unroll
    for (int u = 0; u < 8; ++u) {
        int idx = tid + u * 256;
        int n = idx >> 5, d = idx & 31;
        float acc = 0.f;
        #pragma unroll
        for (int m = 0; m < 64; ++m) acc += s[n][m] * vv[m][d];
        outp[(size_t)n * kC + d] = acc;
    }
}

// ---------------- MSA residual: x2 = x + g_msa * window_reverse(roll_back(proj)) --
__global__ void resid1_kernel(const float* __restrict__ x) {
    int r = blockIdx.x;
    int b = r >> 10, l = r & 1023;
    int i = l >> 5, j = l & 31;
    int i2 = (i - kSS + 32) & 31, j2 = (j - kSS + 32) & 31;   // roll(+SS) gather
    int wrow = ((b * 16 + (i2 >> 3) * 4 + (j2 >> 3)) << 6) + ((i2 & 7) << 3) + (j2 & 7);
    int tid = threadIdx.x;
    int c0 = tid * 4;
    const float* gm = g_ada + b * 6 * kC + 2 * kC;   // g_msa
    float4 xin = *(const float4*)(x + (size_t)r * kC + c0);
    float4 pv  = *(const float4*)(g_proj + (size_t)wrow * kC + c0);
    float4 o;
    o.x = xin.x + gm[c0 + 0] * pv.x;
    o.y = xin.y + gm[c0 + 1] * pv.y;
    o.z = xin.z + gm[c0 + 2] * pv.z;
    o.w = xin.w + gm[c0 + 3] * pv.w;
    *(float4*)(g_x2 + (size_t)r * kC + c0) = o;
}

// ---------------- launch ----------------
extern "C" void kernel_launch(void* const* d_in, const int* in_sizes, int n_in,
                              void* d_out, int out_size) {
    const float* x       = (const float*)d_in[0];
    const float* cond    = (const float*)d_in[1];
    const float* norm1_w = (const float*)d_in[2];
    const float* norm1_b = (const float*)d_in[3];
    const float* qkv_w   = (const float*)d_in[4];
    const float* qkv_b   = (const float*)d_in[5];
    const float* rpb     = (const float*)d_in[6];
    const float* proj_w  = (const float*)d_in[7];
    const float* proj_b  = (const float*)d_in[8];
    const float* norm2_w = (const float*)d_in[9];
    const float* norm2_b = (const float*)d_in[10];
    const float* fc1_w   = (const float*)d_in[11];
    const float* fc1_b   = (const float*)d_in[12];
    const float* fc2_w   = (const float*)d_in[13];
    const float* fc2_b   = (const float*)d_in[14];
    const float* ada_w   = (const float*)d_in[15];
    const float* ada_b   = (const float*)d_in[16];
    float* out = (float*)d_out;

    void *p_hw, *p_qkv, *p_attn, *p_proj, *p_x2, *p_m, *p_fc1;
    cudaGetSymbolAddress(&p_hw,   g_hw);
    cudaGetSymbolAddress(&p_qkv,  g_qkv);
    cudaGetSymbolAddress(&p_attn, g_attn);
    cudaGetSymbolAddress(&p_proj, g_proj);
    cudaGetSymbolAddress(&p_x2,   g_x2);
    cudaGetSymbolAddress(&p_m,    g_m);
    cudaGetSymbolAddress(&p_fc1,  g_fc1);

    // 1. adaLN modulation params
    ada_kernel<<<kB, 256>>>(cond, ada_w, ada_b);
    // 2. LN1 + modulate + roll + window partition -> g_hw [32768, 512]
    ln_mod_kernel<<<kRows, 128>>>(x, norm1_w, norm1_b, (float*)p_hw, 0, 0, kC);
    // 3. qkv = hw @ qkv_w^T + b  [32768, 1536]
    gemm_nt<<<dim3(1536 / 128, kRows / 128), 256>>>((const float*)p_hw, qkv_w, qkv_b,
                                                    (float*)p_qkv, kRows, 1536, 512, 0, nullptr, 0);
    // 4. windowed attention -> g_attn [32768, 512]
    attn_kernel<<<dim3(kB * kNW, kHeads), 256>>>(rpb);
    // 5. proj GEMM -> g_proj
    gemm_nt<<<dim3(512 / 128, kRows / 128), 256>>>((const float*)p_attn, proj_w, proj_b,
                                                   (float*)p_proj, kRows, 512, 512, 0, nullptr, 0);
    // 6. x2 = x + g_msa * reverse(proj)
    resid1_kernel<<<kRows, 128>>>(x);
    // 7. LN2 + modulate -> g_m
    ln_mod_kernel<<<kRows, 128>>>((const float*)p_x2, norm2_w, norm2_b, (float*)p_m,
                                  1, 3 * kC, 4 * kC);
    // 8. fc1 + GELU -> g_fc1 [32768, 2048]
    gemm_nt<<<dim3(2048 / 128, kRows / 128), 256>>>((const float*)p_m, fc1_w, fc1_b,
                                                    (float*)p_fc1, kRows, 2048, 512, 1, nullptr, 0);
    // 9. fc2 + gated residual -> d_out
    gemm_nt<<<dim3(512 / 128, kRows / 128), 256>>>((const float*)p_fc1, fc2_w, fc2_b,
                                                   out, kRows, 512, 2048, 2, (const float*)p_x2, 5 * kC);
}

// round 2
// speedup vs baseline: 1.6912x; 1.6912x over previous
#include <cuda_runtime.h>
#include <math.h>
#include <stdint.h>

// ---------------- problem constants ----------------
constexpr int kB = 32;
constexpr int kC = 512;
constexpr int kHeads = 16;
constexpr int kSS = 4;
constexpr int kNW = 16;           // windows per image
constexpr int kL = 1024;          // tokens per image
constexpr int kRows = kB * kL;    // 32768

// ---------------- scratch ----------------
__device__ __align__(16) float g_ada[kB * 6 * kC];
__device__ __align__(16) float g_hw[(size_t)kRows * kC];
__device__ __align__(16) float g_qkv[(size_t)kRows * 3 * kC];
__device__ __align__(16) float g_attn[(size_t)kRows * kC];
__device__ __align__(16) float g_proj[(size_t)kRows * kC];
__device__ __align__(16) float g_x2[(size_t)kRows * kC];
__device__ __align__(16) float g_m[(size_t)kRows * kC];
__device__ __align__(16) float g_fc1[(size_t)kRows * 4 * kC];

__device__ __forceinline__ float to_tf32(float x) {
    float y;
    asm("cvt.rna.tf32.f32 %0, %1;" : "=f"(y) : "f"(x));
    return y;
}

// ---------------- adaLN: ada = silu(cond) @ ada_w^T + ada_b ----------------
__global__ void ada_kernel(const float* __restrict__ cond,
                           const float* __restrict__ ada_w,
                           const float* __restrict__ ada_b) {
    int b = blockIdx.x;
    __shared__ float sc[kC];
    for (int i = threadIdx.x; i < kC; i += blockDim.x) {
        float c = cond[b * kC + i];
        sc[i] = c / (1.f + expf(-c));
    }
    __syncthreads();
    for (int n = threadIdx.x; n < 6 * kC; n += blockDim.x) {
        const float* wr = ada_w + (size_t)n * kC;
        float acc = 0.f;
        #pragma unroll 8
        for (int k = 0; k < kC; ++k) acc += sc[k] * wr[k];
        g_ada[b * 6 * kC + n] = acc + ada_b[n];
    }
}

// ---------------- LN + modulate (+ optional roll & window-partition gather) ----
__global__ void ln_mod_kernel(const float* __restrict__ x,
                              const float* __restrict__ lnw,
                              const float* __restrict__ lnb,
                              float* __restrict__ out,
                              int mode, int sh_off, int sc_off) {
    int r = blockIdx.x;
    int b, src;
    if (mode == 0) {
        int win = r >> 6, t = r & 63;
        b = win >> 4;
        int nw_ = win & 15;
        int hb = nw_ >> 2, wb = nw_ & 3;
        int i = hb * 8 + (t >> 3), j = wb * 8 + (t & 7);
        int si = (i + kSS) & 31, sj = (j + kSS) & 31;   // roll(-SS) gather
        src = b * kL + si * 32 + sj;
    } else {
        b = r >> 10;
        src = r;
    }
    int tid = threadIdx.x;  // 128 threads, 4 floats each
    float4 v = ((const float4*)(x + (size_t)src * kC))[tid];
    float s = v.x + v.y + v.z + v.w;
    float ss = v.x * v.x + v.y * v.y + v.z * v.z + v.w * v.w;
    #pragma unroll
    for (int o = 16; o; o >>= 1) {
        s  += __shfl_down_sync(0xffffffffu, s, o);
        ss += __shfl_down_sync(0xffffffffu, ss, o);
    }
    __shared__ float ps[4], pss[4], mv[2];
    int wp = tid >> 5;
    if ((tid & 31) == 0) { ps[wp] = s; pss[wp] = ss; }
    __syncthreads();
    if (tid == 0) {
        float S = ps[0] + ps[1] + ps[2] + ps[3];
        float S2 = pss[0] + pss[1] + pss[2] + pss[3];
        float mu = S / kC;
        float var = S2 / kC - mu * mu;
        mv[0] = mu;
        mv[1] = rsqrtf(var + 1e-5f);
    }
    __syncthreads();
    float mu = mv[0], rs = mv[1];
    int c0 = tid * 4;
    const float* sh = g_ada + b * 6 * kC + sh_off;
    const float* sc = g_ada + b * 6 * kC + sc_off;
    float vv[4] = {v.x, v.y, v.z, v.w};
    float o4[4];
    #pragma unroll
    for (int u = 0; u < 4; ++u) {
        float val = (vv[u] - mu) * rs * lnw[c0 + u] + lnb[c0 + u];
        o4[u] = val * (1.f + sc[c0 + u]) + sh[c0 + u];
    }
    ((float4*)(out + (size_t)r * kC))[tid] = make_float4(o4[0], o4[1], o4[2], o4[3]);
}

// ---------------- TF32 tensor-core NT GEMM: C = A[M,K] @ Bw[N,K]^T + bias ------
// Block 128x128, 8 warps (4x2), warp tile 32x64, mma.m16n8k8 tf32.
// epi 0: bias.  epi 1: bias + exact GELU.  epi 2: res + gate*(bias+acc).
constexpr int kS = 136;   // smem row stride (floats): (8*k + m) % 32 covers all banks

__global__ __launch_bounds__(256) void gemm_tf32(
        const float* __restrict__ A, const float* __restrict__ Bw,
        const float* __restrict__ bias, float* __restrict__ C,
        int M, int N, int K, int epi,
        const float* __restrict__ res, int gate_off) {
    __shared__ float As[16 * kS];
    __shared__ float Bs[16 * kS];

    int tid = threadIdx.x;
    int lane = tid & 31;
    int warp = tid >> 5;
    int warp_m = warp & 3;          // 4 warps in M
    int warp_n = warp >> 2;         // 2 warps in N
    int gid = lane >> 2;            // groupID 0..7
    int tig = lane & 3;             // thread-in-group 0..3

    float acc[2][8][4];
    #pragma unroll
    for (int mt = 0; mt < 2; ++mt)
        #pragma unroll
        for (int nt = 0; nt < 8; ++nt)
            #pragma unroll
            for (int i = 0; i < 4; ++i) acc[mt][nt][i] = 0.f;

    const float* Ag = A + (size_t)(blockIdx.y * 128) * K;
    const float* Bg = Bw + (size_t)(blockIdx.x * 128) * K;
    int lr = tid >> 2, lc = (tid & 3) << 2;

    for (int kt = 0; kt < K; kt += 16) {
        #pragma unroll
        for (int h = 0; h < 2; ++h) {
            int row = lr + h * 64;
            float4 va = *(const float4*)(Ag + (size_t)row * K + kt + lc);
            As[(lc + 0) * kS + row] = to_tf32(va.x);
            As[(lc + 1) * kS + row] = to_tf32(va.y);
            As[(lc + 2) * kS + row] = to_tf32(va.z);
            As[(lc + 3) * kS + row] = to_tf32(va.w);
            float4 vb = *(const float4*)(Bg + (size_t)row * K + kt + lc);
            Bs[(lc + 0) * kS + row] = to_tf32(vb.x);
            Bs[(lc + 1) * kS + row] = to_tf32(vb.y);
            Bs[(lc + 2) * kS + row] = to_tf32(vb.z);
            Bs[(lc + 3) * kS + row] = to_tf32(vb.w);
        }
        __syncthreads();
        #pragma unroll
        for (int kk = 0; kk < 16; kk += 8) {
            uint32_t af[2][4];
            #pragma unroll
            for (int mt = 0; mt < 2; ++mt) {
                int m0 = warp_m * 32 + mt * 16 + gid;
                af[mt][0] = __float_as_uint(As[(kk + tig) * kS + m0]);
                af[mt][1] = __float_as_uint(As[(kk + tig) * kS + m0 + 8]);
                af[mt][2] = __float_as_uint(As[(kk + tig + 4) * kS + m0]);
                af[mt][3] = __float_as_uint(As[(kk + tig + 4) * kS + m0 + 8]);
            }
            #pragma unroll
            for (int nt = 0; nt < 8; ++nt) {
                int n0 = warp_n * 64 + nt * 8 + gid;
                uint32_t b0 = __float_as_uint(Bs[(kk + tig) * kS + n0]);
                uint32_t b1 = __float_as_uint(Bs[(kk + tig + 4) * kS + n0]);
                #pragma unroll
                for (int mt = 0; mt < 2; ++mt) {
                    asm volatile(
                        "mma.sync.aligned.m16n8k8.row.col.f32.tf32.tf32.f32 "
                        "{%0,%1,%2,%3}, {%4,%5,%6,%7}, {%8,%9}, {%0,%1,%2,%3};"
                        : "+f"(acc[mt][nt][0]), "+f"(acc[mt][nt][1]),
                          "+f"(acc[mt][nt][2]), "+f"(acc[mt][nt][3])
                        : "r"(af[mt][0]), "r"(af[mt][1]), "r"(af[mt][2]), "r"(af[mt][3]),
                          "r"(b0), "r"(b1));
                }
            }
        }
        __syncthreads();
    }

    // epilogue
    int rbase = blockIdx.y * 128 + warp_m * 32;
    int cbase = blockIdx.x * 128 + warp_n * 64;
    #pragma unroll
    for (int mt = 0; mt < 2; ++mt) {
        #pragma unroll
        for (int half = 0; half < 2; ++half) {
            int r = rbase + mt * 16 + gid + half * 8;
            int b = r >> 10;
            const float* gate = g_ada + b * 6 * kC + gate_off;
            #pragma unroll
            for (int nt = 0; nt < 8; ++nt) {
                int c = cbase + nt * 8 + tig * 2;
                float v0 = acc[mt][nt][half * 2 + 0] + bias[c];
                float v1 = acc[mt][nt][half * 2 + 1] + bias[c + 1];
                if (epi == 1) {
                    v0 = 0.5f * v0 * (1.f + erff(v0 * 0.70710678118654752f));
                    v1 = 0.5f * v1 * (1.f + erff(v1 * 0.70710678118654752f));
                } else if (epi == 2) {
                    v0 = res[(size_t)r * kC + c]     + gate[c]     * v0;
                    v1 = res[(size_t)r * kC + c + 1] + gate[c + 1] * v1;
                }
                *(float2*)(C + (size_t)r * N + c) = make_float2(v0, v1);
            }
        }
    }
}

// ---------------- window attention: one block per (window, head) ----------------
__global__ __launch_bounds__(256) void attn_kernel(const float* __restrict__ rpb) {
    int win = blockIdx.x, head = blockIdx.y;
    __shared__ float q[64][32], kk[64][32], vv[64][32];
    __shared__ float s[64][65];
    __shared__ int sid[64];
    int tid = threadIdx.x;

    const float* base = g_qkv + (size_t)win * 64 * 1536 + head * 32;
    #pragma unroll
    for (int u = 0; u < 8; ++u) {
        int idx = tid + u * 256;
        int n = idx >> 5, d = idx & 31;
        size_t off = (size_t)n * 1536 + d;
        q[n][d]  = base[off];
        kk[n][d] = base[off + 512];
        vv[n][d] = base[off + 1024];
    }
    if (tid < 64) {
        int nw_ = win & 15, hb = nw_ >> 2, wb = nw_ & 3;
        int i = hb * 8 + (tid >> 3), j = wb * 8 + (tid & 7);
        int ri = i < 24 ? 0 : (i < 28 ? 1 : 2);
        int rj = j < 24 ? 0 : (j < 28 ? 1 : 2);
        sid[tid] = ri * 3 + rj;
    }
    __syncthreads();

    const float scale = 0.17677669529663687f;  // 1/sqrt(32)
    #pragma unroll
    for (int u = 0; u < 16; ++u) {
        int idx = tid + u * 256;
        int n = idx >> 6, m = idx & 63;
        float acc = 0.f;
        #pragma unroll
        for (int d = 0; d < 32; ++d) acc += q[n][d] * kk[m][d];
        int di = (n >> 3) - (m >> 3) + 7;
        int dj = (n & 7) - (m & 7) + 7;
        float bias_ = rpb[(di * 15 + dj) * kHeads + head];
        float msk = (sid[n] != sid[m]) ? -100.f : 0.f;
        s[n][m] = acc * scale + bias_ + msk;
    }
    __syncthreads();

    if (tid < 64) {
        float mx = -1e30f;
        #pragma unroll 8
        for (int m = 0; m < 64; ++m) mx = fmaxf(mx, s[tid][m]);
        float sum = 0.f;
        #pragma unroll 8
        for (int m = 0; m < 64; ++m) { float e = expf(s[tid][m] - mx); s[tid][m] = e; sum += e; }
        float inv = 1.f / sum;
        #pragma unroll 8
        for (int m = 0; m < 64; ++m) s[tid][m] *= inv;
    }
    __syncthreads();

    float* outp = g_attn + (size_t)win * 64 * kC + head * 32;
    #pragma unroll
    for (int u = 0; u < 8; ++u) {
        int idx = tid + u * 256;
        int n = idx >> 5, d = idx & 31;
        float acc = 0.f;
        #pragma unroll
        for (int m = 0; m < 64; ++m) acc += s[n][m] * vv[m][d];
        outp[(size_t)n * kC + d] = acc;
    }
}

// ---------------- MSA residual: x2 = x + g_msa * window_reverse(roll_back(proj)) --
__global__ void resid1_kernel(const float* __restrict__ x) {
    int r = blockIdx.x;
    int b = r >> 10, l = r & 1023;
    int i = l >> 5, j = l & 31;
    int i2 = (i - kSS + 32) & 31, j2 = (j - kSS + 32) & 31;   // roll(+SS) gather
    int wrow = ((b * 16 + (i2 >> 3) * 4 + (j2 >> 3)) << 6) + ((i2 & 7) << 3) + (j2 & 7);
    int tid = threadIdx.x;
    int c0 = tid * 4;
    const float* gm = g_ada + b * 6 * kC + 2 * kC;   // g_msa
    float4 xin = *(const float4*)(x + (size_t)r * kC + c0);
    float4 pv  = *(const float4*)(g_proj + (size_t)wrow * kC + c0);
    float4 o;
    o.x = xin.x + gm[c0 + 0] * pv.x;
    o.y = xin.y + gm[c0 + 1] * pv.y;
    o.z = xin.z + gm[c0 + 2] * pv.z;
    o.w = xin.w + gm[c0 + 3] * pv.w;
    *(float4*)(g_x2 + (size_t)r * kC + c0) = o;
}

// ---------------- launch ----------------
extern "C" void kernel_launch(void* const* d_in, const int* in_sizes, int n_in,
                              void* d_out, int out_size) {
    const float* x       = (const float*)d_in[0];
    const float* cond    = (const float*)d_in[1];
    const float* norm1_w = (const float*)d_in[2];
    const float* norm1_b = (const float*)d_in[3];
    const float* qkv_w   = (const float*)d_in[4];
    const float* qkv_b   = (const float*)d_in[5];
    const float* rpb     = (const float*)d_in[6];
    const float* proj_w  = (const float*)d_in[7];
    const float* proj_b  = (const float*)d_in[8];
    const float* norm2_w = (const float*)d_in[9];
    const float* norm2_b = (const float*)d_in[10];
    const float* fc1_w   = (const float*)d_in[11];
    const float* fc1_b   = (const float*)d_in[12];
    const float* fc2_w   = (const float*)d_in[13];
    const float* fc2_b   = (const float*)d_in[14];
    const float* ada_w   = (const float*)d_in[15];
    const float* ada_b   = (const float*)d_in[16];
    float* out = (float*)d_out;

    void *p_hw, *p_qkv, *p_attn, *p_proj, *p_x2, *p_m, *p_fc1;
    cudaGetSymbolAddress(&p_hw,   g_hw);
    cudaGetSymbolAddress(&p_qkv,  g_qkv);
    cudaGetSymbolAddress(&p_attn, g_attn);
    cudaGetSymbolAddress(&p_proj, g_proj);
    cudaGetSymbolAddress(&p_x2,   g_x2);
    cudaGetSymbolAddress(&p_m,    g_m);
    cudaGetSymbolAddress(&p_fc1,  g_fc1);

    // 1. adaLN modulation params
    ada_kernel<<<kB, 256>>>(cond, ada_w, ada_b);
    // 2. LN1 + modulate + roll + window partition -> g_hw [32768, 512]
    ln_mod_kernel<<<kRows, 128>>>(x, norm1_w, norm1_b, (float*)p_hw, 0, 0, kC);
    // 3. qkv = hw @ qkv_w^T + b  [32768, 1536]
    gemm_tf32<<<dim3(1536 / 128, kRows / 128), 256>>>((const float*)p_hw, qkv_w, qkv_b,
                                                      (float*)p_qkv, kRows, 1536, 512, 0, nullptr, 0);
    // 4. windowed attention -> g_attn [32768, 512]
    attn_kernel<<<dim3(kB * kNW, kHeads), 256>>>(rpb);
    // 5. proj GEMM -> g_proj
    gemm_tf32<<<dim3(512 / 128, kRows / 128), 256>>>((const float*)p_attn, proj_w, proj_b,
                                                     (float*)p_proj, kRows, 512, 512, 0, nullptr, 0);
    // 6. x2 = x + g_msa * reverse(proj)
    resid1_kernel<<<kRows, 128>>>(x);
    // 7. LN2 + modulate -> g_m
    ln_mod_kernel<<<kRows, 128>>>((const float*)p_x2, norm2_w, norm2_b, (float*)p_m,
                                  1, 3 * kC, 4 * kC);
    // 8. fc1 + GELU -> g_fc1 [32768, 2048]
    gemm_tf32<<<dim3(2048 / 128, kRows / 128), 256>>>((const float*)p_m, fc1_w, fc1_b,
                                                      (float*)p_fc1, kRows, 2048, 512, 1, nullptr, 0);
    // 9. fc2 + gated residual -> d_out
    gemm_tf32<<<dim3(512 / 128, kRows / 128), 256>>>((const float*)p_fc1, fc2_w, fc2_b,
                                                     out, kRows, 512, 2048, 2, (const float*)p_x2, 5 * kC);
}

// round 3
// speedup vs baseline: 2.2917x; 1.3550x over previous
#include <cuda_runtime.h>
#include <math.h>
#include <stdint.h>

// ---------------- problem constants ----------------
constexpr int kB = 32;
constexpr int kC = 512;
constexpr int kHeads = 16;
constexpr int kSS = 4;
constexpr int kNW = 16;           // windows per image
constexpr int kL = 1024;          // tokens per image
constexpr int kRows = kB * kL;    // 32768

// ---------------- scratch ----------------
__device__ __align__(16) float g_ada[kB * 6 * kC];
__device__ __align__(16) float g_hw[(size_t)kRows * kC];
__device__ __align__(16) float g_qkv[(size_t)kRows * 3 * kC];
__device__ __align__(16) float g_attn[(size_t)kRows * kC];
__device__ __align__(16) float g_proj[(size_t)kRows * kC];
__device__ __align__(16) float g_x2[(size_t)kRows * kC];
__device__ __align__(16) float g_m[(size_t)kRows * kC];
__device__ __align__(16) float g_fc1[(size_t)kRows * 4 * kC];

__device__ __forceinline__ uint32_t tf32_bits(float x) {
    float y;
    asm("cvt.rna.tf32.f32 %0, %1;" : "=f"(y) : "f"(x));
    return __float_as_uint(y);
}

__device__ __forceinline__ void cp16(uint32_t dst_smem, const void* src) {
    asm volatile("cp.async.cg.shared.global [%0], [%1], 16;" :: "r"(dst_smem), "l"(src));
}

// ---------------- adaLN: ada = silu(cond) @ ada_w^T + ada_b ----------------
__global__ void ada_kernel(const float* __restrict__ cond,
                           const float* __restrict__ ada_w,
                           const float* __restrict__ ada_b) {
    int b = blockIdx.x;
    __shared__ float sc[kC];
    for (int i = threadIdx.x; i < kC; i += blockDim.x) {
        float c = cond[b * kC + i];
        sc[i] = c / (1.f + expf(-c));
    }
    __syncthreads();
    for (int n = threadIdx.x; n < 6 * kC; n += blockDim.x) {
        const float* wr = ada_w + (size_t)n * kC;
        float acc = 0.f;
        #pragma unroll 8
        for (int k = 0; k < kC; ++k) acc += sc[k] * wr[k];
        g_ada[b * 6 * kC + n] = acc + ada_b[n];
    }
}

// ---------------- LN + modulate (+ optional roll & window-partition gather) ----
__global__ void ln_mod_kernel(const float* __restrict__ x,
                              const float* __restrict__ lnw,
                              const float* __restrict__ lnb,
                              float* __restrict__ out,
                              int mode, int sh_off, int sc_off) {
    int r = blockIdx.x;
    int b, src;
    if (mode == 0) {
        int win = r >> 6, t = r & 63;
        b = win >> 4;
        int nw_ = win & 15;
        int hb = nw_ >> 2, wb = nw_ & 3;
        int i = hb * 8 + (t >> 3), j = wb * 8 + (t & 7);
        int si = (i + kSS) & 31, sj = (j + kSS) & 31;   // roll(-SS) gather
        src = b * kL + si * 32 + sj;
    } else {
        b = r >> 10;
        src = r;
    }
    int tid = threadIdx.x;  // 128 threads, 4 floats each
    float4 v = ((const float4*)(x + (size_t)src * kC))[tid];
    float s = v.x + v.y + v.z + v.w;
    float ss = v.x * v.x + v.y * v.y + v.z * v.z + v.w * v.w;
    #pragma unroll
    for (int o = 16; o; o >>= 1) {
        s  += __shfl_down_sync(0xffffffffu, s, o);
        ss += __shfl_down_sync(0xffffffffu, ss, o);
    }
    __shared__ float ps[4], pss[4], mv[2];
    int wp = tid >> 5;
    if ((tid & 31) == 0) { ps[wp] = s; pss[wp] = ss; }
    __syncthreads();
    if (tid == 0) {
        float S = ps[0] + ps[1] + ps[2] + ps[3];
        float S2 = pss[0] + pss[1] + pss[2] + pss[3];
        float mu = S / kC;
        float var = S2 / kC - mu * mu;
        mv[0] = mu;
        mv[1] = rsqrtf(var + 1e-5f);
    }
    __syncthreads();
    float mu = mv[0], rs = mv[1];
    int c0 = tid * 4;
    const float* sh = g_ada + b * 6 * kC + sh_off;
    const float* sc = g_ada + b * 6 * kC + sc_off;
    float vv[4] = {v.x, v.y, v.z, v.w};
    float o4[4];
    #pragma unroll
    for (int u = 0; u < 4; ++u) {
        float val = (vv[u] - mu) * rs * lnw[c0 + u] + lnb[c0 + u];
        o4[u] = val * (1.f + sc[c0 + u]) + sh[c0 + u];
    }
    ((float4*)(out + (size_t)r * kC))[tid] = make_float4(o4[0], o4[1], o4[2], o4[3]);
}

// ---------------- TF32 tensor-core NT GEMM, cp.async double-buffered ----------
// Block 128x128, K-tile 32, 8 warps (4x2), warp tile 32x64, mma.m16n8k8 tf32.
// Operand smem layout: row-major [m][k] / [n][k] with stride 36 floats.
// epi 0: bias.  epi 1: bias + exact GELU.  epi 2: res + gate*(bias+acc).
constexpr int kKT = 32;            // K-tile
constexpr int kLS = 36;            // smem row stride (floats)
constexpr int kBufF = 128 * kLS;   // floats per operand buffer

__global__ __launch_bounds__(256) void gemm_tf32(
        const float* __restrict__ A, const float* __restrict__ Bw,
        const float* __restrict__ bias, float* __restrict__ C,
        int M, int N, int K, int epi,
        const float* __restrict__ res, int gate_off) {
    extern __shared__ float smem[];
    float* As = smem;                 // [2][128][36]
    float* Bs = smem + 2 * kBufF;     // [2][128][36]

    int tid = threadIdx.x;
    int lane = tid & 31;
    int warp = tid >> 5;
    int warp_m = warp & 3;            // 4 warps in M
    int warp_n = warp >> 2;           // 2 warps in N
    int gid = lane >> 2;              // groupID 0..7
    int tig = lane & 3;               // thread-in-group 0..3

    float acc[2][8][4];
    #pragma unroll
    for (int mt = 0; mt < 2; ++mt)
        #pragma unroll
        for (int nt = 0; nt < 8; ++nt)
            #pragma unroll
            for (int i = 0; i < 4; ++i) acc[mt][nt][i] = 0.f;

    const float* Ag = A + (size_t)(blockIdx.y * 128) * K;
    const float* Bg = Bw + (size_t)(blockIdx.x * 128) * K;

    uint32_t sA = (uint32_t)__cvta_generic_to_shared(As);
    uint32_t sB = (uint32_t)__cvta_generic_to_shared(Bs);

    int ldr_row = tid >> 3;            // 0..31 (row block of 32 per pass... see below)
    int ldr_col = (tid & 7) * 4;       // 0,4,...,28

    auto load_tile = [&](int buf, int kt) {
        // 128 rows x 32 floats per operand: 1024 float4s, 256 threads, 4 passes
        #pragma unroll
        for (int p = 0; p < 4; ++p) {
            int row = ldr_row + p * 32;
            uint32_t doff = (uint32_t)((buf * kBufF + row * kLS + ldr_col) * 4);
            cp16(sA + doff, Ag + (size_t)row * K + kt + ldr_col);
            cp16(sB + doff, Bg + (size_t)row * K + kt + ldr_col);
        }
        asm volatile("cp.async.commit_group;" ::: "memory");
    };

    int ntile = K / kKT;
    load_tile(0, 0);

    for (int t = 0; t < ntile; ++t) {
        if (t + 1 < ntile) {
            load_tile((t + 1) & 1, (t + 1) * kKT);
            asm volatile("cp.async.wait_group 1;" ::: "memory");
        } else {
            asm volatile("cp.async.wait_group 0;" ::: "memory");
        }
        __syncthreads();

        const float* Ab = As + (t & 1) * kBufF;
        const float* Bb = Bs + (t & 1) * kBufF;

        #pragma unroll
        for (int kk = 0; kk < kKT; kk += 8) {
            uint32_t af[2][4];
            #pragma unroll
            for (int mt = 0; mt < 2; ++mt) {
                int m0 = warp_m * 32 + mt * 16 + gid;
                af[mt][0] = tf32_bits(Ab[(m0    ) * kLS + kk + tig]);
                af[mt][1] = tf32_bits(Ab[(m0 + 8) * kLS + kk + tig]);
                af[mt][2] = tf32_bits(Ab[(m0    ) * kLS + kk + tig + 4]);
                af[mt][3] = tf32_bits(Ab[(m0 + 8) * kLS + kk + tig + 4]);
            }
            #pragma unroll
            for (int nt = 0; nt < 8; ++nt) {
                int n0 = warp_n * 64 + nt * 8 + gid;
                uint32_t b0 = tf32_bits(Bb[n0 * kLS + kk + tig]);
                uint32_t b1 = tf32_bits(Bb[n0 * kLS + kk + tig + 4]);
                #pragma unroll
                for (int mt = 0; mt < 2; ++mt) {
                    asm volatile(
                        "mma.sync.aligned.m16n8k8.row.col.f32.tf32.tf32.f32 "
                        "{%0,%1,%2,%3}, {%4,%5,%6,%7}, {%8,%9}, {%0,%1,%2,%3};"
                        : "+f"(acc[mt][nt][0]), "+f"(acc[mt][nt][1]),
                          "+f"(acc[mt][nt][2]), "+f"(acc[mt][nt][3])
                        : "r"(af[mt][0]), "r"(af[mt][1]), "r"(af[mt][2]), "r"(af[mt][3]),
                          "r"(b0), "r"(b1));
                }
            }
        }
        __syncthreads();
    }

    // epilogue
    int rbase = blockIdx.y * 128 + warp_m * 32;
    int cbase = blockIdx.x * 128 + warp_n * 64;
    #pragma unroll
    for (int mt = 0; mt < 2; ++mt) {
        #pragma unroll
        for (int half = 0; half < 2; ++half) {
            int r = rbase + mt * 16 + gid + half * 8;
            int b = r >> 10;
            const float* gate = g_ada + b * 6 * kC + gate_off;
            #pragma unroll
            for (int nt = 0; nt < 8; ++nt) {
                int c = cbase + nt * 8 + tig * 2;
                float v0 = acc[mt][nt][half * 2 + 0] + bias[c];
                float v1 = acc[mt][nt][half * 2 + 1] + bias[c + 1];
                if (epi == 1) {
                    v0 = 0.5f * v0 * (1.f + erff(v0 * 0.70710678118654752f));
                    v1 = 0.5f * v1 * (1.f + erff(v1 * 0.70710678118654752f));
                } else if (epi == 2) {
                    v0 = res[(size_t)r * kC + c]     + gate[c]     * v0;
                    v1 = res[(size_t)r * kC + c + 1] + gate[c + 1] * v1;
                }
                *(float2*)(C + (size_t)r * N + c) = make_float2(v0, v1);
            }
        }
    }
}

// ---------------- window attention: one block per (window, head) ----------------
__global__ __launch_bounds__(256) void attn_kernel(const float* __restrict__ rpb) {
    int win = blockIdx.x, head = blockIdx.y;
    __shared__ float q[64][32], kk[64][32], vv[64][32];
    __shared__ float s[64][65];
    __shared__ int sid[64];
    int tid = threadIdx.x;

    const float* base = g_qkv + (size_t)win * 64 * 1536 + head * 32;
    #pragma unroll
    for (int u = 0; u < 8; ++u) {
        int idx = tid + u * 256;
        int n = idx >> 5, d = idx & 31;
        size_t off = (size_t)n * 1536 + d;
        q[n][d]  = base[off];
        kk[n][d] = base[off + 512];
        vv[n][d] = base[off + 1024];
    }
    if (tid < 64) {
        int nw_ = win & 15, hb = nw_ >> 2, wb = nw_ & 3;
        int i = hb * 8 + (tid >> 3), j = wb * 8 + (tid & 7);
        int ri = i < 24 ? 0 : (i < 28 ? 1 : 2);
        int rj = j < 24 ? 0 : (j < 28 ? 1 : 2);
        sid[tid] = ri * 3 + rj;
    }
    __syncthreads();

    const float scale = 0.17677669529663687f;  // 1/sqrt(32)
    #pragma unroll
    for (int u = 0; u < 16; ++u) {
        int idx = tid + u * 256;
        int n = idx >> 6, m = idx & 63;
        float acc = 0.f;
        #pragma unroll
        for (int d = 0; d < 32; ++d) acc += q[n][d] * kk[m][d];
        int di = (n >> 3) - (m >> 3) + 7;
        int dj = (n & 7) - (m & 7) + 7;
        float bias_ = rpb[(di * 15 + dj) * kHeads + head];
        float msk = (sid[n] != sid[m]) ? -100.f : 0.f;
        s[n][m] = acc * scale + bias_ + msk;
    }
    __syncthreads();

    if (tid < 64) {
        float mx = -1e30f;
        #pragma unroll 8
        for (int m = 0; m < 64; ++m) mx = fmaxf(mx, s[tid][m]);
        float sum = 0.f;
        #pragma unroll 8
        for (int m = 0; m < 64; ++m) { float e = expf(s[tid][m] - mx); s[tid][m] = e; sum += e; }
        float inv = 1.f / sum;
        #pragma unroll 8
        for (int m = 0; m < 64; ++m) s[tid][m] *= inv;
    }
    __syncthreads();

    float* outp = g_attn + (size_t)win * 64 * kC + head * 32;
    #pragma unroll
    for (int u = 0; u < 8; ++u) {
        int idx = tid + u * 256;
        int n = idx >> 5, d = idx & 31;
        float acc = 0.f;
        #pragma unroll
        for (int m = 0; m < 64; ++m) acc += s[n][m] * vv[m][d];
        outp[(size_t)n * kC + d] = acc;
    }
}

// ---------------- MSA residual: x2 = x + g_msa * window_reverse(roll_back(proj)) --
__global__ void resid1_kernel(const float* __restrict__ x) {
    int r = blockIdx.x;
    int b = r >> 10, l = r & 1023;
    int i = l >> 5, j = l & 31;
    int i2 = (i - kSS + 32) & 31, j2 = (j - kSS + 32) & 31;   // roll(+SS) gather
    int wrow = ((b * 16 + (i2 >> 3) * 4 + (j2 >> 3)) << 6) + ((i2 & 7) << 3) + (j2 & 7);
    int tid = threadIdx.x;
    int c0 = tid * 4;
    const float* gm = g_ada + b * 6 * kC + 2 * kC;   // g_msa
    float4 xin = *(const float4*)(x + (size_t)r * kC + c0);
    float4 pv  = *(const float4*)(g_proj + (size_t)wrow * kC + c0);
    float4 o;
    o.x = xin.x + gm[c0 + 0] * pv.x;
    o.y = xin.y + gm[c0 + 1] * pv.y;
    o.z = xin.z + gm[c0 + 2] * pv.z;
    o.w = xin.w + gm[c0 + 3] * pv.w;
    *(float4*)(g_x2 + (size_t)r * kC + c0) = o;
}

// ---------------- launch ----------------
extern "C" void kernel_launch(void* const* d_in, const int* in_sizes, int n_in,
                              void* d_out, int out_size) {
    const float* x       = (const float*)d_in[0];
    const float* cond    = (const float*)d_in[1];
    const float* norm1_w = (const float*)d_in[2];
    const float* norm1_b = (const float*)d_in[3];
    const float* qkv_w   = (const float*)d_in[4];
    const float* qkv_b   = (const float*)d_in[5];
    const float* rpb     = (const float*)d_in[6];
    const float* proj_w  = (const float*)d_in[7];
    const float* proj_b  = (const float*)d_in[8];
    const float* norm2_w = (const float*)d_in[9];
    const float* norm2_b = (const float*)d_in[10];
    const float* fc1_w   = (const float*)d_in[11];
    const float* fc1_b   = (const float*)d_in[12];
    const float* fc2_w   = (const float*)d_in[13];
    const float* fc2_b   = (const float*)d_in[14];
    const float* ada_w   = (const float*)d_in[15];
    const float* ada_b   = (const float*)d_in[16];
    float* out = (float*)d_out;

    void *p_hw, *p_qkv, *p_attn, *p_proj, *p_x2, *p_m, *p_fc1;
    cudaGetSymbolAddress(&p_hw,   g_hw);
    cudaGetSymbolAddress(&p_qkv,  g_qkv);
    cudaGetSymbolAddress(&p_attn, g_attn);
    cudaGetSymbolAddress(&p_proj, g_proj);
    cudaGetSymbolAddress(&p_x2,   g_x2);
    cudaGetSymbolAddress(&p_m,    g_m);
    cudaGetSymbolAddress(&p_fc1,  g_fc1);

    const int gemm_smem = 4 * kBufF * sizeof(float);   // 73.7 KB
    static bool attr_set = false;
    if (!attr_set) {
        cudaFuncSetAttribute(gemm_tf32, cudaFuncAttributeMaxDynamicSharedMemorySize, gemm_smem);
        attr_set = true;
    }

    // 1. adaLN modulation params
    ada_kernel<<<kB, 256>>>(cond, ada_w, ada_b);
    // 2. LN1 + modulate + roll + window partition -> g_hw [32768, 512]
    ln_mod_kernel<<<kRows, 128>>>(x, norm1_w, norm1_b, (float*)p_hw, 0, 0, kC);
    // 3. qkv = hw @ qkv_w^T + b  [32768, 1536]
    gemm_tf32<<<dim3(1536 / 128, kRows / 128), 256, gemm_smem>>>(
        (const float*)p_hw, qkv_w, qkv_b, (float*)p_qkv, kRows, 1536, 512, 0, nullptr, 0);
    // 4. windowed attention -> g_attn [32768, 512]
    attn_kernel<<<dim3(kB * kNW, kHeads), 256>>>(rpb);
    // 5. proj GEMM -> g_proj
    gemm_tf32<<<dim3(512 / 128, kRows / 128), 256, gemm_smem>>>(
        (const float*)p_attn, proj_w, proj_b, (float*)p_proj, kRows, 512, 512, 0, nullptr, 0);
    // 6. x2 = x + g_msa * reverse(proj)
    resid1_kernel<<<kRows, 128>>>(x);
    // 7. LN2 + modulate -> g_m
    ln_mod_kernel<<<kRows, 128>>>((const float*)p_x2, norm2_w, norm2_b, (float*)p_m,
                                  1, 3 * kC, 4 * kC);
    // 8. fc1 + GELU -> g_fc1 [32768, 2048]
    gemm_tf32<<<dim3(2048 / 128, kRows / 128), 256, gemm_smem>>>(
        (const float*)p_m, fc1_w, fc1_b, (float*)p_fc1, kRows, 2048, 512, 1, nullptr, 0);
    // 9. fc2 + gated residual -> d_out
    gemm_tf32<<<dim3(512 / 128, kRows / 128), 256, gemm_smem>>>(
        (const float*)p_fc1, fc2_w, fc2_b, out, kRows, 512, 2048, 2, (const float*)p_x2, 5 * kC);
}

// round 4
// speedup vs baseline: 2.5616x; 1.1178x over previous
#include <cuda_runtime.h>
#include <math.h>
#include <stdint.h>

// ---------------- problem constants ----------------
constexpr int kB = 32;
constexpr int kC = 512;
constexpr int kHeads = 16;
constexpr int kSS = 4;
constexpr int kNW = 16;           // windows per image
constexpr int kL = 1024;          // tokens per image
constexpr int kRows = kB * kL;    // 32768

// ---------------- scratch ----------------
__device__ __align__(16) float g_ada[kB * 6 * kC];
__device__ __align__(16) float g_hw[(size_t)kRows * kC];
__device__ __align__(16) float g_qkv[(size_t)kRows * 3 * kC];
__device__ __align__(16) float g_attn[(size_t)kRows * kC];
__device__ __align__(16) float g_proj[(size_t)kRows * kC];
__device__ __align__(16) float g_x2[(size_t)kRows * kC];
__device__ __align__(16) float g_m[(size_t)kRows * kC];
__device__ __align__(16) float g_fc1[(size_t)kRows * 4 * kC];
// TF32-rounded weight copies
__device__ __align__(16) float g_wq[1536 * 512];
__device__ __align__(16) float g_wp[512 * 512];
__device__ __align__(16) float g_w1[2048 * 512];
__device__ __align__(16) float g_w2[512 * 2048];

__device__ __forceinline__ float tf32r(float x) {
    float y;
    asm("cvt.rna.tf32.f32 %0, %1;" : "=f"(y) : "f"(x));
    return y;
}

__device__ __forceinline__ void cp16(uint32_t dst_smem, const void* src) {
    asm volatile("cp.async.cg.shared.global [%0], [%1], 16;" :: "r"(dst_smem), "l"(src));
}

__device__ __forceinline__ void mma_tf32(float* c, uint32_t a0, uint32_t a1, uint32_t a2,
                                         uint32_t a3, uint32_t b0, uint32_t b1) {
    asm volatile(
        "mma.sync.aligned.m16n8k8.row.col.f32.tf32.tf32.f32 "
        "{%0,%1,%2,%3}, {%4,%5,%6,%7}, {%8,%9}, {%0,%1,%2,%3};"
        : "+f"(c[0]), "+f"(c[1]), "+f"(c[2]), "+f"(c[3])
        : "r"(a0), "r"(a1), "r"(a2), "r"(a3), "r"(b0), "r"(b1));
}

// ---------------- weight TF32 pre-round ----------------
__global__ void cvtw_kernel(const float* __restrict__ src, float* __restrict__ dst, int n4) {
    int i = blockIdx.x * blockDim.x + threadIdx.x;
    if (i >= n4) return;
    float4 v = ((const float4*)src)[i];
    v.x = tf32r(v.x); v.y = tf32r(v.y); v.z = tf32r(v.z); v.w = tf32r(v.w);
    ((float4*)dst)[i] = v;
}

// ---------------- adaLN: ada = silu(cond) @ ada_w^T + ada_b ----------------
__global__ void ada_kernel(const float* __restrict__ cond,
                           const float* __restrict__ ada_w,
                           const float* __restrict__ ada_b) {
    int b = blockIdx.x;
    __shared__ float sc[kC];
    for (int i = threadIdx.x; i < kC; i += blockDim.x) {
        float c = cond[b * kC + i];
        sc[i] = c / (1.f + expf(-c));
    }
    __syncthreads();
    for (int n = threadIdx.x; n < 6 * kC; n += blockDim.x) {
        const float* wr = ada_w + (size_t)n * kC;
        float acc = 0.f;
        #pragma unroll 8
        for (int k = 0; k < kC; ++k) acc += sc[k] * wr[k];
        g_ada[b * 6 * kC + n] = acc + ada_b[n];
    }
}

// ---------------- LN + modulate (+ optional roll & window-partition gather) ----
// Output is TF32-rounded (feeds a GEMM A operand only).
__global__ void ln_mod_kernel(const float* __restrict__ x,
                              const float* __restrict__ lnw,
                              const float* __restrict__ lnb,
                              float* __restrict__ out,
                              int mode, int sh_off, int sc_off) {
    int r = blockIdx.x;
    int b, src;
    if (mode == 0) {
        int win = r >> 6, t = r & 63;
        b = win >> 4;
        int nw_ = win & 15;
        int hb = nw_ >> 2, wb = nw_ & 3;
        int i = hb * 8 + (t >> 3), j = wb * 8 + (t & 7);
        int si = (i + kSS) & 31, sj = (j + kSS) & 31;   // roll(-SS) gather
        src = b * kL + si * 32 + sj;
    } else {
        b = r >> 10;
        src = r;
    }
    int tid = threadIdx.x;  // 128 threads, 4 floats each
    float4 v = ((const float4*)(x + (size_t)src * kC))[tid];
    float s = v.x + v.y + v.z + v.w;
    float ss = v.x * v.x + v.y * v.y + v.z * v.z + v.w * v.w;
    #pragma unroll
    for (int o = 16; o; o >>= 1) {
        s  += __shfl_down_sync(0xffffffffu, s, o);
        ss += __shfl_down_sync(0xffffffffu, ss, o);
    }
    __shared__ float ps[4], pss[4], mv[2];
    int wp = tid >> 5;
    if ((tid & 31) == 0) { ps[wp] = s; pss[wp] = ss; }
    __syncthreads();
    if (tid == 0) {
        float S = ps[0] + ps[1] + ps[2] + ps[3];
        float S2 = pss[0] + pss[1] + pss[2] + pss[3];
        float mu = S / kC;
        float var = S2 / kC - mu * mu;
        mv[0] = mu;
        mv[1] = rsqrtf(var + 1e-5f);
    }
    __syncthreads();
    float mu = mv[0], rs = mv[1];
    int c0 = tid * 4;
    const float* sh = g_ada + b * 6 * kC + sh_off;
    const float* sc = g_ada + b * 6 * kC + sc_off;
    float vv[4] = {v.x, v.y, v.z, v.w};
    float o4[4];
    #pragma unroll
    for (int u = 0; u < 4; ++u) {
        float val = (vv[u] - mu) * rs * lnw[c0 + u] + lnb[c0 + u];
        o4[u] = tf32r(val * (1.f + sc[c0 + u]) + sh[c0 + u]);
    }
    ((float4*)(out + (size_t)r * kC))[tid] = make_float4(o4[0], o4[1], o4[2], o4[3]);
}

// ---------------- TF32 tensor-core NT GEMM, cp.async double-buffered ----------
// All operands must already be TF32-rounded. Block 128x128, K-tile 32,
// 8 warps (4x2), warp tile 32x64, mma.m16n8k8.
// epi&3: 0 bias. 1 bias+GELU. 2 res+gate*(bias+acc).  epi&8: round output to tf32.
constexpr int kKT = 32;
constexpr int kLS = 36;            // smem row stride (floats)
constexpr int kBufF = 128 * kLS;

__global__ __launch_bounds__(256) void gemm_tf32(
        const float* __restrict__ A, const float* __restrict__ Bw,
        const float* __restrict__ bias, float* __restrict__ C,
        int M, int N, int K, int epi,
        const float* __restrict__ res, int gate_off) {
    extern __shared__ float smem[];
    float* As = smem;                 // [2][128][36]
    float* Bs = smem + 2 * kBufF;     // [2][128][36]

    int tid = threadIdx.x;
    int lane = tid & 31;
    int warp = tid >> 5;
    int warp_m = warp & 3;
    int warp_n = warp >> 2;
    int gid = lane >> 2;
    int tig = lane & 3;

    float acc[2][8][4];
    #pragma unroll
    for (int mt = 0; mt < 2; ++mt)
        #pragma unroll
        for (int nt = 0; nt < 8; ++nt)
            #pragma unroll
            for (int i = 0; i < 4; ++i) acc[mt][nt][i] = 0.f;

    const float* Ag = A + (size_t)(blockIdx.y * 128) * K;
    const float* Bg = Bw + (size_t)(blockIdx.x * 128) * K;

    uint32_t sA = (uint32_t)__cvta_generic_to_shared(As);
    uint32_t sB = (uint32_t)__cvta_generic_to_shared(Bs);

    int ldr_row = tid >> 3;
    int ldr_col = (tid & 7) * 4;

    auto load_tile = [&](int buf, int kt) {
        #pragma unroll
        for (int p = 0; p < 4; ++p) {
            int row = ldr_row + p * 32;
            uint32_t doff = (uint32_t)((buf * kBufF + row * kLS + ldr_col) * 4);
            cp16(sA + doff, Ag + (size_t)row * K + kt + ldr_col);
            cp16(sB + doff, Bg + (size_t)row * K + kt + ldr_col);
        }
        asm volatile("cp.async.commit_group;" ::: "memory");
    };

    int ntile = K / kKT;
    load_tile(0, 0);

    for (int t = 0; t < ntile; ++t) {
        if (t + 1 < ntile) {
            load_tile((t + 1) & 1, (t + 1) * kKT);
            asm volatile("cp.async.wait_group 1;" ::: "memory");
        } else {
            asm volatile("cp.async.wait_group 0;" ::: "memory");
        }
        __syncthreads();

        const float* Ab = As + (t & 1) * kBufF;
        const float* Bb = Bs + (t & 1) * kBufF;

        #pragma unroll
        for (int kk = 0; kk < kKT; kk += 8) {
            uint32_t af[2][4];
            #pragma unroll
            for (int mt = 0; mt < 2; ++mt) {
                int m0 = warp_m * 32 + mt * 16 + gid;
                af[mt][0] = __float_as_uint(Ab[(m0    ) * kLS + kk + tig]);
                af[mt][1] = __float_as_uint(Ab[(m0 + 8) * kLS + kk + tig]);
                af[mt][2] = __float_as_uint(Ab[(m0    ) * kLS + kk + tig + 4]);
                af[mt][3] = __float_as_uint(Ab[(m0 + 8) * kLS + kk + tig + 4]);
            }
            #pragma unroll
            for (int nt = 0; nt < 8; ++nt) {
                int n0 = warp_n * 64 + nt * 8 + gid;
                uint32_t b0 = __float_as_uint(Bb[n0 * kLS + kk + tig]);
                uint32_t b1 = __float_as_uint(Bb[n0 * kLS + kk + tig + 4]);
                #pragma unroll
                for (int mt = 0; mt < 2; ++mt)
                    mma_tf32(acc[mt][nt], af[mt][0], af[mt][1], af[mt][2], af[mt][3], b0, b1);
            }
        }
        __syncthreads();
    }

    int mode = epi & 3;
    bool do_round = (epi & 8) != 0;
    int rbase = blockIdx.y * 128 + warp_m * 32;
    int cbase = blockIdx.x * 128 + warp_n * 64;
    #pragma unroll
    for (int mt = 0; mt < 2; ++mt) {
        #pragma unroll
        for (int half = 0; half < 2; ++half) {
            int r = rbase + mt * 16 + gid + half * 8;
            int b = r >> 10;
            const float* gate = g_ada + b * 6 * kC + gate_off;
            #pragma unroll
            for (int nt = 0; nt < 8; ++nt) {
                int c = cbase + nt * 8 + tig * 2;
                float v0 = acc[mt][nt][half * 2 + 0] + bias[c];
                float v1 = acc[mt][nt][half * 2 + 1] + bias[c + 1];
                if (mode == 1) {
                    v0 = 0.5f * v0 * (1.f + erff(v0 * 0.70710678118654752f));
                    v1 = 0.5f * v1 * (1.f + erff(v1 * 0.70710678118654752f));
                } else if (mode == 2) {
                    v0 = res[(size_t)r * kC + c]     + gate[c]     * v0;
                    v1 = res[(size_t)r * kC + c + 1] + gate[c + 1] * v1;
                }
                if (do_round) { v0 = tf32r(v0); v1 = tf32r(v1); }
                *(float2*)(C + (size_t)r * N + c) = make_float2(v0, v1);
            }
        }
    }
}

// ---------------- window attention via TF32 MMA ----------------
// One block (128 threads, 4 warps) per (window, head).
// QK^T: each warp computes 16x64 of S. Softmax in smem. AV: warp computes 16x32.
constexpr int kQS = 36;   // q/k smem stride
constexpr int kSS2 = 68;  // s & vt smem stride
__global__ __launch_bounds__(128) void attn_kernel(const float* __restrict__ rpb) {
    int win = blockIdx.x, head = blockIdx.y;
    __shared__ float qs[64 * kQS];
    __shared__ float ks[64 * kQS];
    __shared__ float vt[32 * kSS2];   // [d][m]
    __shared__ float s [64 * kSS2];   // [n][m]
    __shared__ int sid[64];
    int tid = threadIdx.x;
    int lane = tid & 31;
    int warp = tid >> 5;
    int gid = lane >> 2;
    int tig = lane & 3;

    const float* base = g_qkv + (size_t)win * 64 * 1536 + head * 32;
    // load q,k (row-major, pad 36) and v transposed (vt[d][m], pad 68)
    for (int i = tid; i < 512; i += 128) {
        int n = i >> 3, c4 = (i & 7) * 4;
        float4 vq = *(const float4*)(base + (size_t)n * 1536 + c4);
        qs[n * kQS + c4 + 0] = vq.x; qs[n * kQS + c4 + 1] = vq.y;
        qs[n * kQS + c4 + 2] = vq.z; qs[n * kQS + c4 + 3] = vq.w;
        float4 vk = *(const float4*)(base + (size_t)n * 1536 + 512 + c4);
        ks[n * kQS + c4 + 0] = vk.x; ks[n * kQS + c4 + 1] = vk.y;
        ks[n * kQS + c4 + 2] = vk.z; ks[n * kQS + c4 + 3] = vk.w;
        float4 vv = *(const float4*)(base + (size_t)n * 1536 + 1024 + c4);
        vt[(c4 + 0) * kSS2 + n] = vv.x; vt[(c4 + 1) * kSS2 + n] = vv.y;
        vt[(c4 + 2) * kSS2 + n] = vv.z; vt[(c4 + 3) * kSS2 + n] = vv.w;
    }
    if (tid < 64) {
        int nw_ = win & 15, hb = nw_ >> 2, wb = nw_ & 3;
        int i = hb * 8 + (tid >> 3), j = wb * 8 + (tid & 7);
        int ri = i < 24 ? 0 : (i < 28 ? 1 : 2);
        int rj = j < 24 ? 0 : (j < 28 ? 1 : 2);
        sid[tid] = ri * 3 + rj;
    }
    __syncthreads();

    // ---- S = Q @ K^T ----
    float c[8][4];
    #pragma unroll
    for (int nt = 0; nt < 8; ++nt)
        #pragma unroll
        for (int i = 0; i < 4; ++i) c[nt][i] = 0.f;

    int m0 = warp * 16 + gid;
    #pragma unroll
    for (int kk = 0; kk < 32; kk += 8) {
        uint32_t a0 = __float_as_uint(qs[(m0    ) * kQS + kk + tig]);
        uint32_t a1 = __float_as_uint(qs[(m0 + 8) * kQS + kk + tig]);
        uint32_t a2 = __float_as_uint(qs[(m0    ) * kQS + kk + tig + 4]);
        uint32_t a3 = __float_as_uint(qs[(m0 + 8) * kQS + kk + tig + 4]);
        #pragma unroll
        for (int nt = 0; nt < 8; ++nt) {
            int n0 = nt * 8 + gid;
            uint32_t b0 = __float_as_uint(ks[n0 * kQS + kk + tig]);
            uint32_t b1 = __float_as_uint(ks[n0 * kQS + kk + tig + 4]);
            mma_tf32(c[nt], a0, a1, a2, a3, b0, b1);
        }
    }

    // epilogue: scale + rel-pos bias + shift mask -> s
    const float scale = 0.17677669529663687f;  // 1/sqrt(32)
    #pragma unroll
    for (int nt = 0; nt < 8; ++nt) {
        #pragma unroll
        for (int idx = 0; idx < 4; ++idx) {
            int row = warp * 16 + gid + ((idx >> 1) << 3);
            int col = nt * 8 + tig * 2 + (idx & 1);
            int di = (row >> 3) - (col >> 3) + 7;
            int dj = (row & 7) - (col & 7) + 7;
            float bias_ = rpb[(di * 15 + dj) * kHeads + head];
            float msk = (sid[row] != sid[col]) ? -100.f : 0.f;
            s[row * kSS2 + col] = c[nt][idx] * scale + bias_ + msk;
        }
    }
    __syncthreads();

    // ---- softmax rows (threads 0..63), output TF32-rounded ----
    if (tid < 64) {
        float* sr = s + tid * kSS2;
        float mx = -1e30f;
        #pragma unroll
        for (int m4 = 0; m4 < 16; ++m4) {
            float4 v = *(float4*)(sr + m4 * 4);
            mx = fmaxf(mx, fmaxf(fmaxf(v.x, v.y), fmaxf(v.z, v.w)));
        }
        float sum = 0.f;
        #pragma unroll
        for (int m4 = 0; m4 < 16; ++m4) {
            float4 v = *(float4*)(sr + m4 * 4);
            v.x = expf(v.x - mx); v.y = expf(v.y - mx);
            v.z = expf(v.z - mx); v.w = expf(v.w - mx);
            sum += v.x + v.y + v.z + v.w;
            *(float4*)(sr + m4 * 4) = v;
        }
        float inv = 1.f / sum;
        #pragma unroll
        for (int m4 = 0; m4 < 16; ++m4) {
            float4 v = *(float4*)(sr + m4 * 4);
            v.x = tf32r(v.x * inv); v.y = tf32r(v.y * inv);
            v.z = tf32r(v.z * inv); v.w = tf32r(v.w * inv);
            *(float4*)(sr + m4 * 4) = v;
        }
    }
    __syncthreads();

    // ---- O = S @ V ----  (A = s[n][m], B = vt[d][m])
    float o[4][4];
    #pragma unroll
    for (int nt = 0; nt < 4; ++nt)
        #pragma unroll
        for (int i = 0; i < 4; ++i) o[nt][i] = 0.f;

    #pragma unroll
    for (int kk = 0; kk < 64; kk += 8) {
        uint32_t a0 = __float_as_uint(s[(m0    ) * kSS2 + kk + tig]);
        uint32_t a1 = __float_as_uint(s[(m0 + 8) * kSS2 + kk + tig]);
        uint32_t a2 = __float_as_uint(s[(m0    ) * kSS2 + kk + tig + 4]);
        uint32_t a3 = __float_as_uint(s[(m0 + 8) * kSS2 + kk + tig + 4]);
        #pragma unroll
        for (int nt = 0; nt < 4; ++nt) {
            int n0 = nt * 8 + gid;
            uint32_t b0 = __float_as_uint(vt[n0 * kSS2 + kk + tig]);
            uint32_t b1 = __float_as_uint(vt[n0 * kSS2 + kk + tig + 4]);
            mma_tf32(o[nt], a0, a1, a2, a3, b0, b1);
        }
    }

    // store (TF32-rounded; feeds proj GEMM A)
    float* outp = g_attn + (size_t)win * 64 * kC + head * 32;
    #pragma unroll
    for (int half = 0; half < 2; ++half) {
        int row = warp * 16 + gid + half * 8;
        #pragma unroll
        for (int nt = 0; nt < 4; ++nt) {
            int col = nt * 8 + tig * 2;
            float v0 = tf32r(o[nt][half * 2 + 0]);
            float v1 = tf32r(o[nt][half * 2 + 1]);
            *(float2*)(outp + (size_t)row * kC + col) = make_float2(v0, v1);
        }
    }
}

// ---------------- MSA residual: x2 = x + g_msa * window_reverse(roll_back(proj)) --
__global__ void resid1_kernel(const float* __restrict__ x) {
    int r = blockIdx.x;
    int b = r >> 10, l = r & 1023;
    int i = l >> 5, j = l & 31;
    int i2 = (i - kSS + 32) & 31, j2 = (j - kSS + 32) & 31;
    int wrow = ((b * 16 + (i2 >> 3) * 4 + (j2 >> 3)) << 6) + ((i2 & 7) << 3) + (j2 & 7);
    int tid = threadIdx.x;
    int c0 = tid * 4;
    const float* gm = g_ada + b * 6 * kC + 2 * kC;
    float4 xin = *(const float4*)(x + (size_t)r * kC + c0);
    float4 pv  = *(const float4*)(g_proj + (size_t)wrow * kC + c0);
    float4 o;
    o.x = xin.x + gm[c0 + 0] * pv.x;
    o.y = xin.y + gm[c0 + 1] * pv.y;
    o.z = xin.z + gm[c0 + 2] * pv.z;
    o.w = xin.w + gm[c0 + 3] * pv.w;
    *(float4*)(g_x2 + (size_t)r * kC + c0) = o;
}

// ---------------- launch ----------------
extern "C" void kernel_launch(void* const* d_in, const int* in_sizes, int n_in,
                              void* d_out, int out_size) {
    const float* x       = (const float*)d_in[0];
    const float* cond    = (const float*)d_in[1];
    const float* norm1_w = (const float*)d_in[2];
    const float* norm1_b = (const float*)d_in[3];
    const float* qkv_w   = (const float*)d_in[4];
    const float* qkv_b   = (const float*)d_in[5];
    const float* rpb     = (const float*)d_in[6];
    const float* proj_w  = (const float*)d_in[7];
    const float* proj_b  = (const float*)d_in[8];
    const float* norm2_w = (const float*)d_in[9];
    const float* norm2_b = (const float*)d_in[10];
    const float* fc1_w   = (const float*)d_in[11];
    const float* fc1_b   = (const float*)d_in[12];
    const float* fc2_w   = (const float*)d_in[13];
    const float* fc2_b   = (const float*)d_in[14];
    const float* ada_w   = (const float*)d_in[15];
    const float* ada_b   = (const float*)d_in[16];
    float* out = (float*)d_out;

    void *p_hw, *p_qkv, *p_attn, *p_proj, *p_x2, *p_m, *p_fc1;
    void *p_wq, *p_wp, *p_w1, *p_w2;
    cudaGetSymbolAddress(&p_hw,   g_hw);
    cudaGetSymbolAddress(&p_qkv,  g_qkv);
    cudaGetSymbolAddress(&p_attn, g_attn);
    cudaGetSymbolAddress(&p_proj, g_proj);
    cudaGetSymbolAddress(&p_x2,   g_x2);
    cudaGetSymbolAddress(&p_m,    g_m);
    cudaGetSymbolAddress(&p_fc1,  g_fc1);
    cudaGetSymbolAddress(&p_wq,   g_wq);
    cudaGetSymbolAddress(&p_wp,   g_wp);
    cudaGetSymbolAddress(&p_w1,   g_w1);
    cudaGetSymbolAddress(&p_w2,   g_w2);

    const int gemm_smem = 4 * kBufF * sizeof(float);   // 73.7 KB
    static bool attr_set = false;
    if (!attr_set) {
        cudaFuncSetAttribute(gemm_tf32, cudaFuncAttributeMaxDynamicSharedMemorySize, gemm_smem);
        attr_set = true;
    }

    // 0. weight TF32 pre-round
    cvtw_kernel<<<(1536 * 512 / 4 + 255) / 256, 256>>>(qkv_w,  (float*)p_wq, 1536 * 512 / 4);
    cvtw_kernel<<<( 512 * 512 / 4 + 255) / 256, 256>>>(proj_w, (float*)p_wp,  512 * 512 / 4);
    cvtw_kernel<<<(2048 * 512 / 4 + 255) / 256, 256>>>(fc1_w,  (float*)p_w1, 2048 * 512 / 4);
    cvtw_kernel<<<( 512 * 2048 / 4 + 255) / 256, 256>>>(fc2_w, (float*)p_w2,  512 * 2048 / 4);

    // 1. adaLN modulation params
    ada_kernel<<<kB, 256>>>(cond, ada_w, ada_b);
    // 2. LN1 + modulate + roll + window partition -> g_hw (tf32)
    ln_mod_kernel<<<kRows, 128>>>(x, norm1_w, norm1_b, (float*)p_hw, 0, 0, kC);
    // 3. qkv = hw @ wq^T + b (tf32-rounded out, feeds attn MMA)
    gemm_tf32<<<dim3(12, 256), 256, gemm_smem>>>(
        (const float*)p_hw, (const float*)p_wq, qkv_b, (float*)p_qkv, kRows, 1536, 512, 0 | 8, nullptr, 0);
    // 4. windowed attention (tf32 MMA) -> g_attn (tf32)
    attn_kernel<<<dim3(kB * kNW, kHeads), 128>>>(rpb);
    // 5. proj GEMM -> g_proj (full fp32, feeds residual)
    gemm_tf32<<<dim3(4, 256), 256, gemm_smem>>>(
        (const float*)p_attn, (const float*)p_wp, proj_b, (float*)p_proj, kRows, 512, 512, 0, nullptr, 0);
    // 6. x2 = x + g_msa * reverse(proj)  (full fp32)
    resid1_kernel<<<kRows, 128>>>(x);
    // 7. LN2 + modulate -> g_m (tf32)
    ln_mod_kernel<<<kRows, 128>>>((const float*)p_x2, norm2_w, norm2_b, (float*)p_m,
                                  1, 3 * kC, 4 * kC);
    // 8. fc1 + GELU -> g_fc1 (tf32)
    gemm_tf32<<<dim3(16, 256), 256, gemm_smem>>>(
        (const float*)p_m, (const float*)p_w1, fc1_b, (float*)p_fc1, kRows, 2048, 512, 1 | 8, nullptr, 0);
    // 9. fc2 + gated residual -> d_out (full fp32)
    gemm_tf32<<<dim3(4, 256), 256, gemm_smem>>>(
        (const float*)p_fc1, (const float*)p_w2, fc2_b, out, kRows, 512, 2048, 2, (const float*)p_x2, 5 * kC);
}